// round 2
// baseline (speedup 1.0000x reference)
#include <cuda_runtime.h>

#define N_AGENT 32
#define BATCH   8192
#define S_DIM   48
#define A_DIM   10
#define G_DIM   128
#define HID     36
#define TB      128
#define NTHREADS 128

// scratch (allocation-free rule: static __device__ arrays)
__device__ float d_sf[N_AGENT * BATCH * HID];   // 37.7 MB
__device__ float d_gf[BATCH * HID];             // 1.2 MB

__device__ __forceinline__ float fast_tanh(float x) {
    // tanh(x) = 1 - 2/(exp(2x)+1), via ex2.approx + rcp.approx (~1e-6 abs err)
    float e, r;
    asm("ex2.approx.f32 %0, %1;" : "=f"(e) : "f"(x * 2.88539008177793f)); // 2*log2(e)
    asm("rcp.approx.f32 %0, %1;" : "=f"(r) : "f"(e + 1.0f));
    return 1.0f - 2.0f * r;
}

struct SmemFeat {
    float W1[HID * S_DIM];
    float b1[HID];
    float W2[HID * HID];
    float b2[HID];
    float tile[TB * 49];   // states in (pad 49), sf staging out (pad 37)
};
struct SmemG {
    float Wg[HID * G_DIM];
    float bg[HID + 4];
};

__global__ __launch_bounds__(NTHREADS)
void feat_kernel(const float* __restrict__ states,
                 const float* __restrict__ gs,
                 const float* __restrict__ W1, const float* __restrict__ b1,
                 const float* __restrict__ W2, const float* __restrict__ b2,
                 const float* __restrict__ Wg, const float* __restrict__ bg)
{
    __shared__ __align__(16) unsigned char smem_raw[sizeof(SmemFeat)];
    const int tid = threadIdx.x;
    const int r0  = blockIdx.x * TB;
    const int ag  = blockIdx.y;

    if (ag < N_AGENT) {
        SmemFeat& sm = *reinterpret_cast<SmemFeat*>(smem_raw);
        const float* gW1 = W1 + ag * HID * S_DIM;
        for (int i = tid; i < HID * S_DIM; i += NTHREADS) sm.W1[i] = gW1[i];
        const float* gW2 = W2 + ag * HID * HID;
        for (int i = tid; i < HID * HID; i += NTHREADS) sm.W2[i] = gW2[i];
        if (tid < HID) { sm.b1[tid] = b1[ag * HID + tid]; sm.b2[tid] = b2[ag * HID + tid]; }
        // coalesced states tile load -> padded smem
        const float* gS = states + (ag * BATCH + r0) * S_DIM;
        for (int i = tid; i < TB * S_DIM; i += NTHREADS) {
            int row = i / S_DIM, col = i - row * S_DIM;
            sm.tile[row * 49 + col] = gS[i];
        }
        __syncthreads();

        float s[S_DIM];
        #pragma unroll
        for (int k = 0; k < S_DIM; k++) s[k] = sm.tile[tid * 49 + k];

        float h[HID];
        const float4* W1v = reinterpret_cast<const float4*>(sm.W1);
        #pragma unroll
        for (int f = 0; f < HID; f++) {
            float acc = sm.b1[f];
            #pragma unroll
            for (int k4 = 0; k4 < S_DIM / 4; k4++) {
                float4 w = W1v[f * (S_DIM / 4) + k4];
                acc += s[4*k4+0]*w.x + s[4*k4+1]*w.y + s[4*k4+2]*w.z + s[4*k4+3]*w.w;
            }
            h[f] = fast_tanh(acc);
        }
        float o[HID];
        const float4* W2v = reinterpret_cast<const float4*>(sm.W2);
        #pragma unroll
        for (int g = 0; g < HID; g++) {
            float acc = sm.b2[g];
            #pragma unroll
            for (int k4 = 0; k4 < HID / 4; k4++) {
                float4 w = W2v[g * (HID / 4) + k4];
                acc += h[4*k4+0]*w.x + h[4*k4+1]*w.y + h[4*k4+2]*w.z + h[4*k4+3]*w.w;
            }
            o[g] = fast_tanh(acc);
        }
        __syncthreads();           // all reads of states tile are done
        #pragma unroll
        for (int g = 0; g < HID; g++) sm.tile[tid * 37 + g] = o[g];
        __syncthreads();
        // coalesced sf store
        float* gsf = d_sf + (ag * BATCH + r0) * HID;
        for (int i = tid; i < TB * HID; i += NTHREADS) {
            int row = i / HID, col = i - row * HID;
            gsf[i] = sm.tile[row * 37 + col];
        }
    } else {
        // global feature: g[b,:] = gs[b,:] @ Wg^T + bg
        SmemG& sm = *reinterpret_cast<SmemG*>(smem_raw);
        for (int i = tid; i < HID * G_DIM; i += NTHREADS) sm.Wg[i] = Wg[i];
        if (tid < HID) sm.bg[tid] = bg[tid];
        __syncthreads();
        const int row = r0 + tid;
        float acc[HID];
        #pragma unroll
        for (int f = 0; f < HID; f++) acc[f] = sm.bg[f];
        const float4* gsv = reinterpret_cast<const float4*>(gs + (size_t)row * G_DIM);
        const float4* Wgv = reinterpret_cast<const float4*>(sm.Wg);
        for (int k4 = 0; k4 < G_DIM / 4; k4++) {
            float4 v = gsv[k4];
            #pragma unroll
            for (int f = 0; f < HID; f++) {
                float4 w = Wgv[f * (G_DIM / 4) + k4];
                acc[f] += v.x*w.x + v.y*w.y + v.z*w.z + v.w*w.w;
            }
        }
        float4* og = reinterpret_cast<float4*>(d_gf + row * HID);
        #pragma unroll
        for (int f4 = 0; f4 < HID / 4; f4++)
            og[f4] = make_float4(acc[4*f4], acc[4*f4+1], acc[4*f4+2], acc[4*f4+3]);
    }
}

struct SmemComm {
    float Wv[3 * HID * HID];   // pre-scaled by topo
    float Wact[A_DIM * HID];
    float bsum[HID];
    float bact[A_DIM + 2];
    float tile[TB * 37];
};

__global__ __launch_bounds__(NTHREADS)
void comm_kernel(const float* __restrict__ Wv, const float* __restrict__ bv,
                 const float* __restrict__ Wact, const float* __restrict__ bact,
                 const float* __restrict__ topo,
                 float* __restrict__ out)
{
    __shared__ __align__(16) SmemComm sm;
    const int tid = threadIdx.x;
    const int r0  = blockIdx.x * TB;
    const int i   = blockIdx.y;
    const int js[3] = { (i + N_AGENT - 1) % N_AGENT, i, (i + 1) % N_AGENT };

    // topo has exactly 3 nonzeros per row (i-1, i, i+1); fold coefficient into Wv
    for (int jj = 0; jj < 3; jj++) {
        int j = js[jj];
        float c = topo[i * N_AGENT + j];
        const float* g = Wv + (size_t)(i * N_AGENT + j) * HID * HID;
        for (int idx = tid; idx < HID * HID; idx += NTHREADS)
            sm.Wv[jj * HID * HID + idx] = c * g[idx];
    }
    if (tid < HID) {
        float acc = 0.f;
        for (int jj = 0; jj < 3; jj++) {
            int j = js[jj];
            acc += topo[i * N_AGENT + j] * bv[(i * N_AGENT + j) * HID + tid];
        }
        sm.bsum[tid] = acc;
    }
    for (int idx = tid; idx < A_DIM * HID; idx += NTHREADS)
        sm.Wact[idx] = Wact[i * A_DIM * HID + idx];
    if (tid < A_DIM) sm.bact[tid] = bact[i * A_DIM + tid];
    __syncthreads();

    float comm[HID];
    #pragma unroll
    for (int g = 0; g < HID; g++) comm[g] = sm.bsum[g];

    for (int jj = 0; jj < 3; jj++) {
        const int j = js[jj];
        const float* gsf = d_sf + (j * BATCH + r0) * HID;
        for (int idx = tid; idx < TB * HID; idx += NTHREADS) {
            int row = idx / HID, col = idx - row * HID;
            sm.tile[row * 37 + col] = gsf[idx];
        }
        __syncthreads();
        float sfr[HID];
        #pragma unroll
        for (int k = 0; k < HID; k++) sfr[k] = sm.tile[tid * 37 + k];
        const float4* Wvv = reinterpret_cast<const float4*>(sm.Wv + jj * HID * HID);
        #pragma unroll
        for (int g = 0; g < HID; g++) {
            float acc = 0.f;
            #pragma unroll
            for (int k4 = 0; k4 < HID / 4; k4++) {
                float4 w = Wvv[g * (HID / 4) + k4];
                acc += sfr[4*k4]*w.x + sfr[4*k4+1]*w.y + sfr[4*k4+2]*w.z + sfr[4*k4+3]*w.w;
            }
            comm[g] += acc;
        }
        __syncthreads();   // tile reads done before next iteration overwrites
    }

    const int row = r0 + tid;
    float x[HID];
    const float4* gv = reinterpret_cast<const float4*>(d_gf + row * HID);
    #pragma unroll
    for (int f4 = 0; f4 < HID / 4; f4++) {
        float4 v = gv[f4];
        x[4*f4+0] = comm[4*f4+0] + v.x;
        x[4*f4+1] = comm[4*f4+1] + v.y;
        x[4*f4+2] = comm[4*f4+2] + v.z;
        x[4*f4+3] = comm[4*f4+3] + v.w;
    }
    const float4* Wav = reinterpret_cast<const float4*>(sm.Wact);
    float* orow = out + (size_t)row * (N_AGENT * A_DIM) + i * A_DIM;
    #pragma unroll
    for (int a = 0; a < A_DIM; a++) {
        float acc = sm.bact[a];
        #pragma unroll
        for (int k4 = 0; k4 < HID / 4; k4++) {
            float4 w = Wav[a * (HID / 4) + k4];
            acc += x[4*k4]*w.x + x[4*k4+1]*w.y + x[4*k4+2]*w.z + x[4*k4+3]*w.w;
        }
        orow[a] = fast_tanh(acc);
    }
}

extern "C" void kernel_launch(void* const* d_in, const int* in_sizes, int n_in,
                              void* d_out, int out_size)
{
    const float* states = (const float*)d_in[0];
    const float* gs     = (const float*)d_in[1];
    const float* W1     = (const float*)d_in[2];
    const float* b1     = (const float*)d_in[3];
    const float* W2     = (const float*)d_in[4];
    const float* b2     = (const float*)d_in[5];
    const float* Wv     = (const float*)d_in[6];
    const float* bv     = (const float*)d_in[7];
    const float* Wg     = (const float*)d_in[8];
    const float* bg     = (const float*)d_in[9];
    const float* Wact   = (const float*)d_in[10];
    const float* bact   = (const float*)d_in[11];
    const float* topo   = (const float*)d_in[12];

    feat_kernel<<<dim3(BATCH / TB, N_AGENT + 1), NTHREADS>>>(
        states, gs, W1, b1, W2, b2, Wg, bg);
    comm_kernel<<<dim3(BATCH / TB, N_AGENT), NTHREADS>>>(
        Wv, bv, Wact, bact, topo, (float*)d_out);
}

// round 4
// speedup vs baseline: 1.4543x; 1.4543x over previous
#include <cuda_runtime.h>

#define N_AGENT 32
#define BATCH   8192
#define S_DIM   48
#define A_DIM   10
#define G_DIM   128
#define HID     36
#define TB      128
#define NTHREADS 128

// scratch (allocation-free rule: static __device__ arrays)
__device__ float d_sf[N_AGENT * BATCH * HID];          // 37.7 MB
__device__ float d_gf[BATCH * HID];                    // 1.2 MB
__device__ float d_A[N_AGENT * 4 * A_DIM * HID];       // folded Wact@(topo*Wv); slot 3 = Wact
__device__ float d_beff[N_AGENT * A_DIM];              // bact + Wact@(sum topo*bv)

__device__ __forceinline__ float fast_tanh(float x) {
    float e, r;
    asm("ex2.approx.f32 %0, %1;" : "=f"(e) : "f"(x * 2.88539008177793f)); // 2*log2(e)
    asm("rcp.approx.f32 %0, %1;" : "=f"(r) : "f"(e + 1.0f));
    return 1.0f - 2.0f * r;
}

// ---------------------------------------------------------------------------
// Precompute A[i][jj] = Wact_i @ (topo_ij * Wv_ij)  (10x36), slot jj=3 = Wact_i,
// and beff[i] = bact_i + Wact_i @ (sum_j topo_ij * bv_ij).
// grid (32, 3), block 360. ~1.2 MFLOP total.
// ---------------------------------------------------------------------------
__global__ __launch_bounds__(360)
void pre_kernel(const float* __restrict__ Wv, const float* __restrict__ bv,
                const float* __restrict__ Wact, const float* __restrict__ bact,
                const float* __restrict__ topo)
{
    __shared__ float sWa[A_DIM * HID];
    __shared__ float sWv[HID * HID];
    const int tid = threadIdx.x;
    const int i  = blockIdx.x;
    const int jj = blockIdx.y;
    const int j  = (i + N_AGENT - 1 + jj) % N_AGENT;
    const float c = topo[i * N_AGENT + j];

    if (tid < A_DIM * HID) sWa[tid] = Wact[i * A_DIM * HID + tid];
    const float* gWv = Wv + (size_t)(i * N_AGENT + j) * HID * HID;
    for (int idx = tid; idx < HID * HID; idx += 360) sWv[idx] = c * gWv[idx];
    __syncthreads();

    if (tid < A_DIM * HID) {
        const int a = tid / HID, f = tid - a * HID;
        float acc = 0.f;
        #pragma unroll
        for (int g = 0; g < HID; g++) acc += sWa[a * HID + g] * sWv[g * HID + f];
        d_A[((i * 4 + jj) * A_DIM * HID) + tid] = acc;
        if (jj == 0) {
            // slot 3 = plain Wact (used for the global-feature term)
            d_A[((i * 4 + 3) * A_DIM * HID) + tid] = sWa[tid];
        }
    }
    if (jj == 0 && tid < A_DIM) {
        float acc = bact[i * A_DIM + tid];
        for (int q = 0; q < 3; q++) {
            int jq = (i + N_AGENT - 1 + q) % N_AGENT;
            float cq = topo[i * N_AGENT + jq];
            const float* gbv = bv + (size_t)(i * N_AGENT + jq) * HID;
            #pragma unroll
            for (int g = 0; g < HID; g++)
                acc += sWa[tid * HID + g] * (cq * gbv[g]);
        }
        d_beff[i * A_DIM + tid] = acc;
    }
}

// ---------------------------------------------------------------------------
// Feature MLP + global feature
// ---------------------------------------------------------------------------
struct SmemFeat {
    float W1[HID * S_DIM];
    float b1[HID];
    float W2[HID * HID];
    float b2[HID];
    float tile[TB * 52];   // pads: states 52, h 44, out 36 (all odd in 16B words)
};
struct SmemG {
    float Wg[HID * G_DIM];
    float bg[HID + 4];
};

__global__ __launch_bounds__(NTHREADS)
void feat_kernel(const float* __restrict__ states,
                 const float* __restrict__ gs,
                 const float* __restrict__ W1, const float* __restrict__ b1,
                 const float* __restrict__ W2, const float* __restrict__ b2,
                 const float* __restrict__ Wg, const float* __restrict__ bg)
{
    __shared__ __align__(16) unsigned char smem_raw[sizeof(SmemFeat)];
    const int tid = threadIdx.x;
    const int r0  = blockIdx.x * TB;
    const int ag  = blockIdx.y;

    if (ag < N_AGENT) {
        SmemFeat& sm = *reinterpret_cast<SmemFeat*>(smem_raw);
        const float* gW1 = W1 + ag * HID * S_DIM;
        for (int i = tid; i < HID * S_DIM; i += NTHREADS) sm.W1[i] = gW1[i];
        const float* gW2 = W2 + ag * HID * HID;
        for (int i = tid; i < HID * HID; i += NTHREADS) sm.W2[i] = gW2[i];
        if (tid < HID) { sm.b1[tid] = b1[ag * HID + tid]; sm.b2[tid] = b2[ag * HID + tid]; }
        const float* gS = states + (size_t)(ag * BATCH + r0) * S_DIM;
        for (int i = tid; i < TB * S_DIM; i += NTHREADS) {
            int row = i / S_DIM, col = i - row * S_DIM;
            sm.tile[row * 52 + col] = gS[i];
        }
        __syncthreads();

        // layer 1: acc[36], stream s in float4 chunks
        float acc[HID];
        #pragma unroll
        for (int f = 0; f < HID; f++) acc[f] = sm.b1[f];
        const float4* W1v = reinterpret_cast<const float4*>(sm.W1);
        #pragma unroll
        for (int k4 = 0; k4 < S_DIM / 4; k4++) {
            float4 s4 = *reinterpret_cast<const float4*>(&sm.tile[tid * 52 + k4 * 4]);
            #pragma unroll
            for (int f = 0; f < HID; f++) {
                float4 w = W1v[f * (S_DIM / 4) + k4];
                acc[f] += s4.x*w.x + s4.y*w.y + s4.z*w.z + s4.w*w.w;
            }
        }
        __syncthreads();   // done reading states tile
        #pragma unroll
        for (int f = 0; f < HID; f++) sm.tile[tid * 44 + f] = fast_tanh(acc[f]);
        __syncthreads();

        // layer 2: stream h in float4 chunks
        #pragma unroll
        for (int f = 0; f < HID; f++) acc[f] = sm.b2[f];
        const float4* W2v = reinterpret_cast<const float4*>(sm.W2);
        #pragma unroll
        for (int k4 = 0; k4 < HID / 4; k4++) {
            float4 h4 = *reinterpret_cast<const float4*>(&sm.tile[tid * 44 + k4 * 4]);
            #pragma unroll
            for (int f = 0; f < HID; f++) {
                float4 w = W2v[f * (HID / 4) + k4];
                acc[f] += h4.x*w.x + h4.y*w.y + h4.z*w.z + h4.w*w.w;
            }
        }
        __syncthreads();   // done reading h tile
        #pragma unroll
        for (int f = 0; f < HID; f++) sm.tile[tid * 36 + f] = fast_tanh(acc[f]);
        __syncthreads();
        float* gsf = d_sf + (size_t)(ag * BATCH + r0) * HID;
        for (int i = tid; i < TB * HID; i += NTHREADS) gsf[i] = sm.tile[i];
    } else {
        // global feature: g[b,:] = gs[b,:] @ Wg^T + bg
        SmemG& sm = *reinterpret_cast<SmemG*>(smem_raw);
        for (int i = tid; i < HID * G_DIM; i += NTHREADS) sm.Wg[i] = Wg[i];
        if (tid < HID) sm.bg[tid] = bg[tid];
        __syncthreads();
        const int row = r0 + tid;
        float acc[HID];
        #pragma unroll
        for (int f = 0; f < HID; f++) acc[f] = sm.bg[f];
        const float4* gsv = reinterpret_cast<const float4*>(gs + (size_t)row * G_DIM);
        const float4* Wgv = reinterpret_cast<const float4*>(sm.Wg);
        for (int k4 = 0; k4 < G_DIM / 4; k4++) {
            float4 v = gsv[k4];
            #pragma unroll
            for (int f = 0; f < HID; f++) {
                float4 w = Wgv[f * (G_DIM / 4) + k4];
                acc[f] += v.x*w.x + v.y*w.y + v.z*w.z + v.w*w.w;
            }
        }
        float4* og = reinterpret_cast<float4*>(d_gf + (size_t)row * HID);
        #pragma unroll
        for (int f4 = 0; f4 < HID / 4; f4++)
            og[f4] = make_float4(acc[4*f4], acc[4*f4+1], acc[4*f4+2], acc[4*f4+3]);
    }
}

// ---------------------------------------------------------------------------
// Fused comm+action: acts = tanh( sum_{jj<3} A[jj]@sf_j + Wact@g + beff )
// ---------------------------------------------------------------------------
struct SmemComm {
    float A[4 * A_DIM * HID];   // 5760 B
    float be[A_DIM + 2];
    float tile[TB * 44];        // 22528 B (44 floats = 11 x 16B words: odd -> conflict-free)
};

__global__ __launch_bounds__(NTHREADS, 8)
void comm_kernel(float* __restrict__ out)
{
    __shared__ __align__(16) SmemComm sm;
    const int tid = threadIdx.x;
    const int r0  = blockIdx.x * TB;
    const int i   = blockIdx.y;

    const float* gA = d_A + (size_t)i * 4 * A_DIM * HID;
    for (int idx = tid; idx < 4 * A_DIM * HID; idx += NTHREADS) sm.A[idx] = gA[idx];
    if (tid < A_DIM) sm.be[tid] = d_beff[i * A_DIM + tid];
    __syncthreads();

    float acc[A_DIM];
    #pragma unroll
    for (int a = 0; a < A_DIM; a++) acc[a] = sm.be[a];

    #pragma unroll
    for (int jj = 0; jj < 4; jj++) {
        const float* src;
        if (jj < 3) {
            const int j = (i + N_AGENT - 1 + jj) % N_AGENT;
            src = d_sf + (size_t)(j * BATCH + r0) * HID;
        } else {
            src = d_gf + (size_t)r0 * HID;
        }
        for (int idx = tid; idx < TB * HID; idx += NTHREADS) {
            int row = idx / HID, col = idx - row * HID;
            sm.tile[row * 44 + col] = src[idx];
        }
        __syncthreads();
        const float4* Av = reinterpret_cast<const float4*>(&sm.A[jj * A_DIM * HID]);
        #pragma unroll
        for (int k4 = 0; k4 < HID / 4; k4++) {
            float4 s4 = *reinterpret_cast<const float4*>(&sm.tile[tid * 44 + k4 * 4]);
            #pragma unroll
            for (int a = 0; a < A_DIM; a++) {
                float4 w = Av[a * (HID / 4) + k4];
                acc[a] += s4.x*w.x + s4.y*w.y + s4.z*w.z + s4.w*w.w;
            }
        }
        __syncthreads();   // tile reads done before next overwrite
    }

    const int row = r0 + tid;
    float* orow = out + (size_t)row * (N_AGENT * A_DIM) + i * A_DIM;
    float2* orow2 = reinterpret_cast<float2*>(orow);   // i*40 bytes -> 8B aligned
    #pragma unroll
    for (int a2 = 0; a2 < A_DIM / 2; a2++)
        orow2[a2] = make_float2(fast_tanh(acc[2*a2]), fast_tanh(acc[2*a2+1]));
}

extern "C" void kernel_launch(void* const* d_in, const int* in_sizes, int n_in,
                              void* d_out, int out_size)
{
    const float* states = (const float*)d_in[0];
    const float* gs     = (const float*)d_in[1];
    const float* W1     = (const float*)d_in[2];
    const float* b1     = (const float*)d_in[3];
    const float* W2     = (const float*)d_in[4];
    const float* b2     = (const float*)d_in[5];
    const float* Wv     = (const float*)d_in[6];
    const float* bv     = (const float*)d_in[7];
    const float* Wg     = (const float*)d_in[8];
    const float* bg     = (const float*)d_in[9];
    const float* Wact   = (const float*)d_in[10];
    const float* bact   = (const float*)d_in[11];
    const float* topo   = (const float*)d_in[12];

    pre_kernel<<<dim3(N_AGENT, 3), 360>>>(Wv, bv, Wact, bact, topo);
    feat_kernel<<<dim3(BATCH / TB, N_AGENT + 1), NTHREADS>>>(
        states, gs, W1, b1, W2, b2, Wg, bg);
    comm_kernel<<<dim3(BATCH / TB, N_AGENT), NTHREADS>>>((float*)d_out);
}

// round 5
// speedup vs baseline: 1.7573x; 1.2083x over previous
#include <cuda_runtime.h>

#define N_AGENT 32
#define BATCH   8192
#define S_DIM   48
#define A_DIM   10
#define G_DIM   128
#define HID     36
#define TB      128
#define NTHREADS 128

typedef unsigned long long ull;

// scratch (allocation-free rule: static __device__ arrays)
__device__ float d_sf[N_AGENT * BATCH * HID];            // 37.7 MB
__device__ float d_gf[BATCH * HID];                      // 1.2 MB
__device__ float d_A[N_AGENT * 4 * HID * 12];            // A^T[i][slice][f][a(pad12)]
__device__ float d_beff[N_AGENT * A_DIM];                // bact + Wact@(sum topo*bv)

__device__ __forceinline__ ull fma2(ull a, ull b, ull c) {
    ull d;
    asm("fma.rn.f32x2 %0, %1, %2, %3;" : "=l"(d) : "l"(a), "l"(b), "l"(c));
    return d;
}
__device__ __forceinline__ ull splat2(float x) {
    ull r; asm("mov.b64 %0, {%1, %1};" : "=l"(r) : "f"(x)); return r;
}
__device__ __forceinline__ ull pack2(float x, float y) {
    ull r; asm("mov.b64 %0, {%1, %2};" : "=l"(r) : "f"(x), "f"(y)); return r;
}
__device__ __forceinline__ float2 unpack2(ull v) {
    float2 r; asm("mov.b64 {%0, %1}, %2;" : "=f"(r.x), "=f"(r.y) : "l"(v)); return r;
}

__device__ __forceinline__ float fast_tanh(float x) {
    float e, r;
    asm("ex2.approx.f32 %0, %1;" : "=f"(e) : "f"(x * 2.88539008177793f)); // 2*log2(e)
    asm("rcp.approx.f32 %0, %1;" : "=f"(r) : "f"(e + 1.0f));
    return 1.0f - 2.0f * r;
}

// ---------------------------------------------------------------------------
// Fused: y==0 -> precompute A^T + beff (x<32); y in [1,32] -> agent feature
// MLP; y==33 -> global feature.
// ---------------------------------------------------------------------------
#define FEAT_SMEM_FLOATS (3104 + TB * 52)

__global__ __launch_bounds__(NTHREADS)
void feat_kernel(const float* __restrict__ states,
                 const float* __restrict__ gs,
                 const float* __restrict__ W1, const float* __restrict__ b1,
                 const float* __restrict__ W2, const float* __restrict__ b2,
                 const float* __restrict__ Wg, const float* __restrict__ bg,
                 const float* __restrict__ Wv, const float* __restrict__ bv,
                 const float* __restrict__ Wact, const float* __restrict__ bact,
                 const float* __restrict__ topo)
{
    __shared__ __align__(16) float sm[FEAT_SMEM_FLOATS];
    const int tid = threadIdx.x;
    const int yb  = blockIdx.y;

    if (yb == 0) {
        // ---------------- pre slice: A^T[i][jj][f][a] + beff ----------------
        const int i = blockIdx.x;
        if (i >= N_AGENT) return;
        float* sWa = sm;          // Wact_i [10][36]
        float* sWv = sm + 384;    // Wv     [36][36]
        for (int idx = tid; idx < A_DIM * HID; idx += NTHREADS)
            sWa[idx] = Wact[i * A_DIM * HID + idx];
        __syncthreads();
        for (int jj = 0; jj < 3; jj++) {
            const int j = (i + N_AGENT - 1 + jj) % N_AGENT;
            const float c = topo[i * N_AGENT + j];
            const float* gWv = Wv + (size_t)(i * N_AGENT + j) * HID * HID;
            for (int idx = tid; idx < HID * HID; idx += NTHREADS)
                sWv[idx] = c * gWv[idx];
            __syncthreads();
            // A^T[f][a] = sum_g Wa[a][g] * c*Wv[g][f], pad a=10,11 with 0
            for (int idx = tid; idx < HID * 12; idx += NTHREADS) {
                const int f = idx / 12, a = idx - f * 12;
                float acc = 0.f;
                if (a < A_DIM) {
                    #pragma unroll
                    for (int g = 0; g < HID; g++)
                        acc += sWa[a * HID + g] * sWv[g * HID + f];
                }
                d_A[((i * 4 + jj) * HID + f) * 12 + a] = acc;
            }
            __syncthreads();
        }
        // slot 3 = Wact^T (for the global-feature term)
        for (int idx = tid; idx < HID * 12; idx += NTHREADS) {
            const int f = idx / 12, a = idx - f * 12;
            d_A[((i * 4 + 3) * HID + f) * 12 + a] = (a < A_DIM) ? sWa[a * HID + f] : 0.f;
        }
        if (tid < A_DIM) {
            float acc = bact[i * A_DIM + tid];
            for (int q = 0; q < 3; q++) {
                const int jq = (i + N_AGENT - 1 + q) % N_AGENT;
                const float cq = topo[i * N_AGENT + jq];
                const float* gbv = bv + (size_t)(i * N_AGENT + jq) * HID;
                #pragma unroll
                for (int g = 0; g < HID; g++)
                    acc += sWa[tid * HID + g] * (cq * gbv[g]);
            }
            d_beff[i * A_DIM + tid] = acc;
        }
        return;
    }

    const int r0 = blockIdx.x * TB;

    if (yb <= N_AGENT) {
        // ---------------- agent feature MLP ----------------
        const int ag = yb - 1;
        float* W1T  = sm;           // [48][36]
        float* W2T  = sm + 1728;    // [36][36]
        float* b1s  = sm + 3024;    // 36
        float* b2s  = sm + 3060;    // 36 (+8 pad)
        float* tile = sm + 3104;    // 128x52 / 128x44 / 128x36

        // coalesced read, transposed scatter-store
        const float* gW1 = W1 + ag * HID * S_DIM;
        for (int idx = tid; idx < HID * S_DIM; idx += NTHREADS) {
            const int f = idx / S_DIM, k = idx - f * S_DIM;
            W1T[k * HID + f] = gW1[idx];
        }
        const float* gW2 = W2 + ag * HID * HID;
        for (int idx = tid; idx < HID * HID; idx += NTHREADS) {
            const int f = idx / HID, k = idx - f * HID;
            W2T[k * HID + f] = gW2[idx];
        }
        if (tid < HID) { b1s[tid] = b1[ag * HID + tid]; b2s[tid] = b2[ag * HID + tid]; }
        const float* gS = states + (size_t)(ag * BATCH + r0) * S_DIM;
        for (int idx = tid; idx < TB * S_DIM; idx += NTHREADS) {
            const int row = idx / S_DIM, col = idx - row * S_DIM;
            tile[row * 52 + col] = gS[idx];
        }
        __syncthreads();

        // layer 1: acc pairs over f, f32x2 FMA
        ull acc[18];
        const ull* b1u = (const ull*)b1s;
        #pragma unroll
        for (int p = 0; p < 18; p++) acc[p] = b1u[p];
        #pragma unroll
        for (int k4 = 0; k4 < S_DIM / 4; k4++) {
            float4 s4 = *(const float4*)&tile[tid * 52 + k4 * 4];
            #pragma unroll
            for (int kk = 0; kk < 4; kk++) {
                const int k = k4 * 4 + kk;
                const ull sk = splat2(((const float*)&s4)[kk]);
                const ulonglong2* w = (const ulonglong2*)&W1T[k * HID];
                #pragma unroll
                for (int p2 = 0; p2 < 9; p2++) {
                    ulonglong2 wv = w[p2];
                    acc[2*p2]   = fma2(wv.x, sk, acc[2*p2]);
                    acc[2*p2+1] = fma2(wv.y, sk, acc[2*p2+1]);
                }
            }
        }
        __syncthreads();   // done reading states tile
        #pragma unroll
        for (int p2 = 0; p2 < 9; p2++) {
            float2 a0 = unpack2(acc[2*p2]), a1 = unpack2(acc[2*p2+1]);
            ulonglong2 st;
            st.x = pack2(fast_tanh(a0.x), fast_tanh(a0.y));
            st.y = pack2(fast_tanh(a1.x), fast_tanh(a1.y));
            *(ulonglong2*)&tile[tid * 44 + p2 * 4] = st;
        }
        __syncthreads();

        // layer 2
        const ull* b2u = (const ull*)b2s;
        #pragma unroll
        for (int p = 0; p < 18; p++) acc[p] = b2u[p];
        #pragma unroll
        for (int k4 = 0; k4 < HID / 4; k4++) {
            float4 h4 = *(const float4*)&tile[tid * 44 + k4 * 4];
            #pragma unroll
            for (int kk = 0; kk < 4; kk++) {
                const int k = k4 * 4 + kk;
                const ull hk = splat2(((const float*)&h4)[kk]);
                const ulonglong2* w = (const ulonglong2*)&W2T[k * HID];
                #pragma unroll
                for (int p2 = 0; p2 < 9; p2++) {
                    ulonglong2 wv = w[p2];
                    acc[2*p2]   = fma2(wv.x, hk, acc[2*p2]);
                    acc[2*p2+1] = fma2(wv.y, hk, acc[2*p2+1]);
                }
            }
        }
        __syncthreads();   // done reading h tile
        #pragma unroll
        for (int p2 = 0; p2 < 9; p2++) {
            float2 a0 = unpack2(acc[2*p2]), a1 = unpack2(acc[2*p2+1]);
            ulonglong2 st;
            st.x = pack2(fast_tanh(a0.x), fast_tanh(a0.y));
            st.y = pack2(fast_tanh(a1.x), fast_tanh(a1.y));
            *(ulonglong2*)&tile[tid * 36 + p2 * 4] = st;
        }
        __syncthreads();
        float* gsf = d_sf + (size_t)(ag * BATCH + r0) * HID;
        for (int idx = tid; idx < TB * HID; idx += NTHREADS) gsf[idx] = tile[idx];
    } else {
        // ---------------- global feature ----------------
        float* WgT = sm;           // [128][36]
        float* bgs = sm + 4608;
        for (int idx = tid; idx < HID * G_DIM; idx += NTHREADS) {
            const int f = idx / G_DIM, k = idx - f * G_DIM;
            WgT[k * HID + f] = Wg[idx];
        }
        if (tid < HID) bgs[tid] = bg[tid];
        __syncthreads();
        const int row = r0 + tid;
        ull acc[18];
        const ull* bgu = (const ull*)bgs;
        #pragma unroll
        for (int p = 0; p < 18; p++) acc[p] = bgu[p];
        const float4* gsv = (const float4*)(gs + (size_t)row * G_DIM);
        for (int k4 = 0; k4 < G_DIM / 4; k4++) {
            float4 v = gsv[k4];
            #pragma unroll
            for (int kk = 0; kk < 4; kk++) {
                const int k = k4 * 4 + kk;
                const ull vk = splat2(((const float*)&v)[kk]);
                const ulonglong2* w = (const ulonglong2*)&WgT[k * HID];
                #pragma unroll
                for (int p2 = 0; p2 < 9; p2++) {
                    ulonglong2 wv = w[p2];
                    acc[2*p2]   = fma2(wv.x, vk, acc[2*p2]);
                    acc[2*p2+1] = fma2(wv.y, vk, acc[2*p2+1]);
                }
            }
        }
        ulonglong2* og = (ulonglong2*)(d_gf + (size_t)row * HID);
        #pragma unroll
        for (int p2 = 0; p2 < 9; p2++) {
            ulonglong2 st; st.x = acc[2*p2]; st.y = acc[2*p2+1];
            og[p2] = st;
        }
    }
}

// ---------------------------------------------------------------------------
// Fused comm+action: acts = tanh( sum_{jj<3} A[jj]@sf_j + Wact@g + beff )
// A stored transposed [f][a(pad12)]; acc pairs over the 10 actions.
// ---------------------------------------------------------------------------
struct SmemComm {
    float A[4 * HID * 12];      // 6912 B
    float be[12];
    float tile[TB * 44];        // 22528 B
};

__global__ __launch_bounds__(NTHREADS, 7)
void comm_kernel(float* __restrict__ out)
{
    __shared__ __align__(16) SmemComm sm;
    const int tid = threadIdx.x;
    const int r0  = blockIdx.x * TB;
    const int i   = blockIdx.y;

    const float* gA = d_A + (size_t)i * 4 * HID * 12;
    for (int idx = tid; idx < 4 * HID * 12; idx += NTHREADS) sm.A[idx] = gA[idx];
    if (tid < A_DIM) sm.be[tid] = d_beff[i * A_DIM + tid];
    __syncthreads();

    ull acc[5];
    const ull* beu = (const ull*)sm.be;
    #pragma unroll
    for (int p = 0; p < 5; p++) acc[p] = beu[p];

    #pragma unroll
    for (int jj = 0; jj < 4; jj++) {
        const float* src;
        if (jj < 3) {
            const int j = (i + N_AGENT - 1 + jj) % N_AGENT;
            src = d_sf + (size_t)(j * BATCH + r0) * HID;
        } else {
            src = d_gf + (size_t)r0 * HID;
        }
        for (int idx = tid; idx < TB * HID; idx += NTHREADS) {
            const int row = idx / HID, col = idx - row * HID;
            sm.tile[row * 44 + col] = src[idx];
        }
        __syncthreads();
        const float* Ap = &sm.A[jj * HID * 12];
        #pragma unroll
        for (int k4 = 0; k4 < HID / 4; k4++) {
            float4 s4 = *(const float4*)&sm.tile[tid * 44 + k4 * 4];
            #pragma unroll
            for (int kk = 0; kk < 4; kk++) {
                const int k = k4 * 4 + kk;
                const ull sk = splat2(((const float*)&s4)[kk]);
                const ulonglong2* w = (const ulonglong2*)&Ap[k * 12];
                ulonglong2 w01 = w[0];
                ulonglong2 w23 = w[1];
                ull w4 = ((const ull*)&Ap[k * 12])[4];
                acc[0] = fma2(w01.x, sk, acc[0]);
                acc[1] = fma2(w01.y, sk, acc[1]);
                acc[2] = fma2(w23.x, sk, acc[2]);
                acc[3] = fma2(w23.y, sk, acc[3]);
                acc[4] = fma2(w4,    sk, acc[4]);
            }
        }
        __syncthreads();   // tile reads done before next overwrite
    }

    const int row = r0 + tid;
    float2* orow2 = (float2*)(out + (size_t)row * (N_AGENT * A_DIM) + i * A_DIM);
    #pragma unroll
    for (int p = 0; p < 5; p++) {
        float2 a = unpack2(acc[p]);
        orow2[p] = make_float2(fast_tanh(a.x), fast_tanh(a.y));
    }
}

extern "C" void kernel_launch(void* const* d_in, const int* in_sizes, int n_in,
                              void* d_out, int out_size)
{
    const float* states = (const float*)d_in[0];
    const float* gs     = (const float*)d_in[1];
    const float* W1     = (const float*)d_in[2];
    const float* b1     = (const float*)d_in[3];
    const float* W2     = (const float*)d_in[4];
    const float* b2     = (const float*)d_in[5];
    const float* Wv     = (const float*)d_in[6];
    const float* bv     = (const float*)d_in[7];
    const float* Wg     = (const float*)d_in[8];
    const float* bg     = (const float*)d_in[9];
    const float* Wact   = (const float*)d_in[10];
    const float* bact   = (const float*)d_in[11];
    const float* topo   = (const float*)d_in[12];

    feat_kernel<<<dim3(BATCH / TB, N_AGENT + 2), NTHREADS>>>(
        states, gs, W1, b1, W2, b2, Wg, bg, Wv, bv, Wact, bact, topo);
    comm_kernel<<<dim3(BATCH / TB, N_AGENT), NTHREADS>>>((float*)d_out);
}

// round 6
// speedup vs baseline: 2.0719x; 1.1790x over previous
#include <cuda_runtime.h>

#define N_AGENT 32
#define BATCH   8192
#define S_DIM   48
#define A_DIM   10
#define G_DIM   128
#define HID     36
#define TB2     256
#define NTHREADS 128

typedef unsigned long long ull;

// scratch (allocation-free rule: static __device__ arrays)
__device__ float d_sf[N_AGENT * BATCH * HID];      // 37.7 MB
__device__ float d_gf[BATCH * HID];                // 1.2 MB
// A packed for f32x2 k-pairing: [i][slice][kp(18)][a2(5)][4]
//   c=0:(a=2a2,k=2kp) c=1:(a=2a2,k=2kp+1) c=2:(a=2a2+1,k=2kp) c=3:(a=2a2+1,k=2kp+1)
__device__ float d_A[N_AGENT * 4 * 18 * 20];
__device__ float d_beff[N_AGENT * A_DIM];

__device__ __forceinline__ ull fma2(ull a, ull b, ull c) {
    ull d;
    asm("fma.rn.f32x2 %0, %1, %2, %3;" : "=l"(d) : "l"(a), "l"(b), "l"(c));
    return d;
}
__device__ __forceinline__ ull splat2(float x) {
    ull r; asm("mov.b64 %0, {%1, %1};" : "=l"(r) : "f"(x)); return r;
}
__device__ __forceinline__ ull pack2(float x, float y) {
    ull r; asm("mov.b64 %0, {%1, %2};" : "=l"(r) : "f"(x), "f"(y)); return r;
}
__device__ __forceinline__ float2 unpack2(ull v) {
    float2 r; asm("mov.b64 {%0, %1}, %2;" : "=f"(r.x), "=f"(r.y) : "l"(v)); return r;
}
__device__ __forceinline__ float fast_tanh(float x) {
    float e, r;
    asm("ex2.approx.f32 %0, %1;" : "=f"(e) : "f"(x * 2.88539008177793f)); // 2*log2(e)
    asm("rcp.approx.f32 %0, %1;" : "=f"(r) : "f"(e + 1.0f));
    return 1.0f - 2.0f * r;
}

// ---------------------------------------------------------------------------
// feat: y==0 -> precompute packed A + beff; y in [1,32] -> agent MLP (2 rows
// per thread); y==33 -> global feature.
// ---------------------------------------------------------------------------
#define FEAT_SMEM_FLOATS (3104 + TB2 * 52)
#define FEAT_SMEM_BYTES  (FEAT_SMEM_FLOATS * 4)

__global__ void feat_kernel(const float* __restrict__ states,
                            const float* __restrict__ gs,
                            const float* __restrict__ W1, const float* __restrict__ b1,
                            const float* __restrict__ W2, const float* __restrict__ b2,
                            const float* __restrict__ Wg, const float* __restrict__ bg,
                            const float* __restrict__ Wv, const float* __restrict__ bv,
                            const float* __restrict__ Wact, const float* __restrict__ bact,
                            const float* __restrict__ topo)
{
    extern __shared__ __align__(16) float sm[];
    const int tid = threadIdx.x;
    const int yb  = blockIdx.y;

    if (yb == 0) {
        // ------- pre slice: packed A + beff for agent i = blockIdx.x -------
        const int i = blockIdx.x;
        float* sWa = sm;          // Wact_i [10][36]
        float* sWv = sm + 384;    // Wv     [36][36]
        for (int idx = tid; idx < A_DIM * HID; idx += NTHREADS)
            sWa[idx] = Wact[i * A_DIM * HID + idx];
        __syncthreads();
        for (int jj = 0; jj < 3; jj++) {
            const int j = (i + N_AGENT - 1 + jj) % N_AGENT;
            const float c = topo[i * N_AGENT + j];
            const float* gWv = Wv + (size_t)(i * N_AGENT + j) * HID * HID;
            for (int idx = tid; idx < HID * HID; idx += NTHREADS)
                sWv[idx] = c * gWv[idx];
            __syncthreads();
            for (int idx = tid; idx < 360; idx += NTHREADS) {
                const int kp = idx / 20, q = idx - kp * 20;
                const int a = 2 * (q >> 2) + ((q & 3) >> 1);
                const int k = 2 * kp + (q & 1);
                float acc = 0.f;
                #pragma unroll
                for (int g = 0; g < HID; g++)
                    acc += sWa[a * HID + g] * sWv[g * HID + k];
                d_A[(i * 4 + jj) * 360 + idx] = acc;
            }
            __syncthreads();
        }
        // slot 3 = plain Wact in packed layout (global-feature term)
        for (int idx = tid; idx < 360; idx += NTHREADS) {
            const int kp = idx / 20, q = idx - kp * 20;
            const int a = 2 * (q >> 2) + ((q & 3) >> 1);
            const int k = 2 * kp + (q & 1);
            d_A[(i * 4 + 3) * 360 + idx] = sWa[a * HID + k];
        }
        if (tid < A_DIM) {
            float acc = bact[i * A_DIM + tid];
            for (int q = 0; q < 3; q++) {
                const int jq = (i + N_AGENT - 1 + q) % N_AGENT;
                const float cq = topo[i * N_AGENT + jq];
                const float* gbv = bv + (size_t)(i * N_AGENT + jq) * HID;
                #pragma unroll
                for (int g = 0; g < HID; g++)
                    acc += sWa[tid * HID + g] * (cq * gbv[g]);
            }
            d_beff[i * A_DIM + tid] = acc;
        }
        return;
    }

    const int r0 = blockIdx.x * TB2;

    if (yb <= N_AGENT) {
        // ------- agent feature MLP, 2 rows per thread -------
        const int ag = yb - 1;
        float* W1T  = sm;           // [48][36]
        float* W2T  = sm + 1728;    // [36][36]
        float* b1s  = sm + 3024;
        float* b2s  = sm + 3060;
        float* tile = sm + 3104;    // layer1: 256x52 ; h: 256x36
        float4* tile4 = (float4*)tile;

        const float* gW1 = W1 + ag * HID * S_DIM;
        for (int idx = tid; idx < HID * S_DIM; idx += NTHREADS) {
            const int f = idx / S_DIM, k = idx - f * S_DIM;
            W1T[k * HID + f] = gW1[idx];
        }
        const float* gW2 = W2 + ag * HID * HID;
        for (int idx = tid; idx < HID * HID; idx += NTHREADS) {
            const int f = idx / HID, k = idx - f * HID;
            W2T[k * HID + f] = gW2[idx];
        }
        if (tid < HID) { b1s[tid] = b1[ag * HID + tid]; b2s[tid] = b2[ag * HID + tid]; }
        // stage states: 256x48 -> stride-52 tile (13 x 16B units, odd)
        const float4* gS4 = (const float4*)(states + (size_t)(ag * BATCH + r0) * S_DIM);
        for (int idx = tid; idx < TB2 * (S_DIM / 4); idx += NTHREADS) {
            const int row = idx / 12, c4 = idx - row * 12;
            tile4[row * 13 + c4] = gS4[idx];
        }
        __syncthreads();

        // layer 1
        ull acc0[18], acc1[18];
        {
            const ull* bu = (const ull*)b1s;
            #pragma unroll
            for (int p = 0; p < 18; p++) { acc0[p] = bu[p]; acc1[p] = bu[p]; }
        }
        #pragma unroll
        for (int k4 = 0; k4 < S_DIM / 4; k4++) {
            float4 sA = tile4[tid * 13 + k4];
            float4 sB = tile4[(tid + NTHREADS) * 13 + k4];
            #pragma unroll
            for (int kk = 0; kk < 4; kk++) {
                const ull a_s = splat2(((const float*)&sA)[kk]);
                const ull b_s = splat2(((const float*)&sB)[kk]);
                const ulonglong2* w = (const ulonglong2*)&W1T[(k4 * 4 + kk) * HID];
                #pragma unroll
                for (int p2 = 0; p2 < 9; p2++) {
                    ulonglong2 wv = w[p2];
                    acc0[2*p2]   = fma2(wv.x, a_s, acc0[2*p2]);
                    acc0[2*p2+1] = fma2(wv.y, a_s, acc0[2*p2+1]);
                    acc1[2*p2]   = fma2(wv.x, b_s, acc1[2*p2]);
                    acc1[2*p2+1] = fma2(wv.y, b_s, acc1[2*p2+1]);
                }
            }
        }
        __syncthreads();   // layer1 tile reads done
        #pragma unroll
        for (int p2 = 0; p2 < 9; p2++) {
            float2 x0 = unpack2(acc0[2*p2]), x1 = unpack2(acc0[2*p2+1]);
            float2 y0 = unpack2(acc1[2*p2]), y1 = unpack2(acc1[2*p2+1]);
            ulonglong2 s0, s1;
            s0.x = pack2(fast_tanh(x0.x), fast_tanh(x0.y));
            s0.y = pack2(fast_tanh(x1.x), fast_tanh(x1.y));
            s1.x = pack2(fast_tanh(y0.x), fast_tanh(y0.y));
            s1.y = pack2(fast_tanh(y1.x), fast_tanh(y1.y));
            *(ulonglong2*)&tile[tid * HID + p2 * 4] = s0;
            *(ulonglong2*)&tile[(tid + NTHREADS) * HID + p2 * 4] = s1;
        }
        __syncthreads();

        // layer 2 (h tile stride 36 = 9 x 16B units, odd)
        {
            const ull* bu = (const ull*)b2s;
            #pragma unroll
            for (int p = 0; p < 18; p++) { acc0[p] = bu[p]; acc1[p] = bu[p]; }
        }
        #pragma unroll
        for (int k4 = 0; k4 < HID / 4; k4++) {
            float4 sA = tile4[tid * 9 + k4];
            float4 sB = tile4[(tid + NTHREADS) * 9 + k4];
            #pragma unroll
            for (int kk = 0; kk < 4; kk++) {
                const ull a_s = splat2(((const float*)&sA)[kk]);
                const ull b_s = splat2(((const float*)&sB)[kk]);
                const ulonglong2* w = (const ulonglong2*)&W2T[(k4 * 4 + kk) * HID];
                #pragma unroll
                for (int p2 = 0; p2 < 9; p2++) {
                    ulonglong2 wv = w[p2];
                    acc0[2*p2]   = fma2(wv.x, a_s, acc0[2*p2]);
                    acc0[2*p2+1] = fma2(wv.y, a_s, acc0[2*p2+1]);
                    acc1[2*p2]   = fma2(wv.x, b_s, acc1[2*p2]);
                    acc1[2*p2+1] = fma2(wv.y, b_s, acc1[2*p2+1]);
                }
            }
        }
        // direct store (rows 144B apart; 16B aligned)
        float* o0 = d_sf + (size_t)(ag * BATCH + r0 + tid) * HID;
        float* o1 = d_sf + (size_t)(ag * BATCH + r0 + tid + NTHREADS) * HID;
        #pragma unroll
        for (int p2 = 0; p2 < 9; p2++) {
            float2 x0 = unpack2(acc0[2*p2]), x1 = unpack2(acc0[2*p2+1]);
            float2 y0 = unpack2(acc1[2*p2]), y1 = unpack2(acc1[2*p2+1]);
            ulonglong2 s0, s1;
            s0.x = pack2(fast_tanh(x0.x), fast_tanh(x0.y));
            s0.y = pack2(fast_tanh(x1.x), fast_tanh(x1.y));
            s1.x = pack2(fast_tanh(y0.x), fast_tanh(y0.y));
            s1.y = pack2(fast_tanh(y1.x), fast_tanh(y1.y));
            *(ulonglong2*)&o0[p2 * 4] = s0;
            *(ulonglong2*)&o1[p2 * 4] = s1;
        }
    } else {
        // ------- global feature, 2 rows per thread -------
        float* WgT = sm;           // [128][36]
        float* bgs = sm + 4608;
        for (int idx = tid; idx < HID * G_DIM; idx += NTHREADS) {
            const int f = idx / G_DIM, k = idx - f * G_DIM;
            WgT[k * HID + f] = Wg[idx];
        }
        if (tid < HID) bgs[tid] = bg[tid];
        __syncthreads();
        ull acc0[18], acc1[18];
        {
            const ull* bu = (const ull*)bgs;
            #pragma unroll
            for (int p = 0; p < 18; p++) { acc0[p] = bu[p]; acc1[p] = bu[p]; }
        }
        const float4* g0 = (const float4*)(gs + (size_t)(r0 + tid) * G_DIM);
        const float4* g1 = (const float4*)(gs + (size_t)(r0 + tid + NTHREADS) * G_DIM);
        for (int k4 = 0; k4 < G_DIM / 4; k4++) {
            float4 vA = g0[k4];
            float4 vB = g1[k4];
            #pragma unroll
            for (int kk = 0; kk < 4; kk++) {
                const ull a_s = splat2(((const float*)&vA)[kk]);
                const ull b_s = splat2(((const float*)&vB)[kk]);
                const ulonglong2* w = (const ulonglong2*)&WgT[(k4 * 4 + kk) * HID];
                #pragma unroll
                for (int p2 = 0; p2 < 9; p2++) {
                    ulonglong2 wv = w[p2];
                    acc0[2*p2]   = fma2(wv.x, a_s, acc0[2*p2]);
                    acc0[2*p2+1] = fma2(wv.y, a_s, acc0[2*p2+1]);
                    acc1[2*p2]   = fma2(wv.x, b_s, acc1[2*p2]);
                    acc1[2*p2+1] = fma2(wv.y, b_s, acc1[2*p2+1]);
                }
            }
        }
        float* o0 = d_gf + (size_t)(r0 + tid) * HID;
        float* o1 = d_gf + (size_t)(r0 + tid + NTHREADS) * HID;
        #pragma unroll
        for (int p2 = 0; p2 < 9; p2++) {
            ulonglong2 s0, s1;
            s0.x = acc0[2*p2]; s0.y = acc0[2*p2+1];
            s1.x = acc1[2*p2]; s1.y = acc1[2*p2+1];
            *(ulonglong2*)&o0[p2 * 4] = s0;
            *(ulonglong2*)&o1[p2 * 4] = s1;
        }
    }
}

// ---------------------------------------------------------------------------
// comm: k-paired f32x2, 2 rows per thread, zero splats.
// ---------------------------------------------------------------------------
struct SmemComm {
    float A[4 * 360];           // 5760 B, packed [jj][kp][a2][4]
    float be[16];
    float tile[TB2 * HID];      // 36864 B, stride 36 (9 x 16B units, odd)
};

__global__ __launch_bounds__(NTHREADS, 4)
void comm_kernel(float* __restrict__ out)
{
    __shared__ __align__(16) SmemComm sm;
    const int tid = threadIdx.x;
    const int r0  = blockIdx.x * TB2;
    const int i   = blockIdx.y;
    float4* tile4 = (float4*)sm.tile;

    const float4* gA = (const float4*)(d_A + (size_t)i * 4 * 360);
    float4* sA4 = (float4*)sm.A;
    for (int idx = tid; idx < 360; idx += NTHREADS) sA4[idx] = gA[idx];
    if (tid < A_DIM) sm.be[tid] = d_beff[i * A_DIM + tid];
    __syncthreads();

    ull acc0[A_DIM], acc1[A_DIM];
    #pragma unroll
    for (int a = 0; a < A_DIM; a++) { acc0[a] = 0ull; acc1[a] = 0ull; }

    #pragma unroll
    for (int jj = 0; jj < 4; jj++) {
        const float* src;
        if (jj < 3) {
            const int j = (i + N_AGENT - 1 + jj) % N_AGENT;
            src = d_sf + (size_t)(j * BATCH + r0) * HID;
        } else {
            src = d_gf + (size_t)r0 * HID;
        }
        const float4* src4 = (const float4*)src;
        for (int idx = tid; idx < TB2 * HID / 4; idx += NTHREADS) tile4[idx] = src4[idx];
        __syncthreads();

        const float4* Af = (const float4*)&sm.A[jj * 360];   // [kp][a2]
        #pragma unroll
        for (int i4 = 0; i4 < 9; i4++) {
            float4 sv0 = tile4[tid * 9 + i4];
            float4 sv1 = tile4[(tid + NTHREADS) * 9 + i4];
            ulonglong2 su0 = *(ulonglong2*)&sv0;   // (kp=2i4, kp=2i4+1) pairs
            ulonglong2 su1 = *(ulonglong2*)&sv1;
            #pragma unroll
            for (int h = 0; h < 2; h++) {
                const ull s0 = h ? su0.y : su0.x;
                const ull s1 = h ? su1.y : su1.x;
                const int kp = 2 * i4 + h;
                #pragma unroll
                for (int a2 = 0; a2 < 5; a2++) {
                    float4 wq = Af[kp * 5 + a2];
                    ulonglong2 wu = *(ulonglong2*)&wq;
                    acc0[2*a2]   = fma2(wu.x, s0, acc0[2*a2]);
                    acc0[2*a2+1] = fma2(wu.y, s0, acc0[2*a2+1]);
                    acc1[2*a2]   = fma2(wu.x, s1, acc1[2*a2]);
                    acc1[2*a2+1] = fma2(wu.y, s1, acc1[2*a2+1]);
                }
            }
        }
        __syncthreads();   // tile reads done before next overwrite
    }

    float2* o0 = (float2*)(out + (size_t)(r0 + tid) * (N_AGENT * A_DIM) + i * A_DIM);
    float2* o1 = (float2*)(out + (size_t)(r0 + tid + NTHREADS) * (N_AGENT * A_DIM) + i * A_DIM);
    #pragma unroll
    for (int p = 0; p < 5; p++) {
        float2 u0 = unpack2(acc0[2*p]),   v0 = unpack2(acc0[2*p+1]);
        float2 u1 = unpack2(acc1[2*p]),   v1 = unpack2(acc1[2*p+1]);
        o0[p] = make_float2(fast_tanh(u0.x + u0.y + sm.be[2*p]),
                            fast_tanh(v0.x + v0.y + sm.be[2*p+1]));
        o1[p] = make_float2(fast_tanh(u1.x + u1.y + sm.be[2*p]),
                            fast_tanh(v1.x + v1.y + sm.be[2*p+1]));
    }
}

extern "C" void kernel_launch(void* const* d_in, const int* in_sizes, int n_in,
                              void* d_out, int out_size)
{
    const float* states = (const float*)d_in[0];
    const float* gs     = (const float*)d_in[1];
    const float* W1     = (const float*)d_in[2];
    const float* b1     = (const float*)d_in[3];
    const float* W2     = (const float*)d_in[4];
    const float* b2     = (const float*)d_in[5];
    const float* Wv     = (const float*)d_in[6];
    const float* bv     = (const float*)d_in[7];
    const float* Wg     = (const float*)d_in[8];
    const float* bg     = (const float*)d_in[9];
    const float* Wact   = (const float*)d_in[10];
    const float* bact   = (const float*)d_in[11];
    const float* topo   = (const float*)d_in[12];

    cudaFuncSetAttribute(feat_kernel, cudaFuncAttributeMaxDynamicSharedMemorySize,
                         FEAT_SMEM_BYTES);
    feat_kernel<<<dim3(BATCH / TB2, N_AGENT + 2), NTHREADS, FEAT_SMEM_BYTES>>>(
        states, gs, W1, b1, W2, b2, Wg, bg, Wv, bv, Wact, bact, topo);
    comm_kernel<<<dim3(BATCH / TB2, N_AGENT), NTHREADS>>>((float*)d_out);
}